// round 16
// baseline (speedup 1.0000x reference)
#include <cuda_runtime.h>
#include <cuda_bf16.h>
#include <math.h>
#include <stdint.h>

#define DIMV 2880
#define SEQ  1024
#define NH   64
#define NKV  8
#define HD   64
#define QKVD 5120
#define QD   4096
#define KDOFF 512
#define INTER 2880
#define NEXP 4
#define LIMITF 7.0f
#define ALPHAF 1.702f
#define SM_SCALE 0.125f

#define NQKVW (2L * DIMV * QKVD)
#define NOUTW (2L * QD * DIMV)
#define NW1   (2L * NEXP * DIMV * 2 * INTER)
#define NW2   (2L * NEXP * INTER * DIMV)

// ---- scratch ----
__device__ __align__(16) float g_t32[SEQ * DIMV];
__device__ __align__(16) __nv_bfloat16 g_th[SEQ * DIMV];
__device__ __align__(16) __nv_bfloat16 g_tl[SEQ * DIMV];
__device__ __align__(16) float g_qkv[SEQ * QKVD];
__device__ __align__(16) __nv_bfloat16 g_ah[SEQ * QD];
__device__ __align__(16) __nv_bfloat16 g_al[SEQ * QD];
__device__ __align__(16) __nv_bfloat16 g_acth[NEXP * SEQ * INTER];
__device__ __align__(16) __nv_bfloat16 g_actl[NEXP * SEQ * INTER];
__device__ __align__(16) float g_cos[SEQ * 32];
__device__ __align__(16) float g_sin[SEQ * 32];
__device__ int   g_sel[SEQ * 2];
__device__ float g_selw[SEQ * 2];
__device__ int   g_list[NEXP * SEQ];
__device__ float g_wgt[NEXP * SEQ];
__device__ int   g_cnt[NEXP];
__device__ __align__(16) __nv_bfloat16 g_qkvw_h[NQKVW];
__device__ __align__(16) __nv_bfloat16 g_qkvw_l[NQKVW];
__device__ __align__(16) __nv_bfloat16 g_outw_h[NOUTW];
__device__ __align__(16) __nv_bfloat16 g_outw_l[NOUTW];
__device__ __align__(16) __nv_bfloat16 g_w1_h[NW1];
__device__ __align__(16) __nv_bfloat16 g_w1_l[NW1];
__device__ __align__(16) __nv_bfloat16 g_w2_h[NW2];
__device__ __align__(16) __nv_bfloat16 g_w2_l[NW2];

// ---------------- helpers ----------------
__device__ __forceinline__ uint32_t smem_u32(const void* p) {
    uint32_t a;
    asm("{ .reg .u64 t; cvta.to.shared.u64 t, %1; cvt.u32.u64 %0, t; }" : "=r"(a) : "l"(p));
    return a;
}
__device__ __forceinline__ void ldsm4(uint32_t* r, uint32_t a) {
    asm volatile("ldmatrix.sync.aligned.m8n8.x4.shared.b16 {%0,%1,%2,%3}, [%4];"
                 : "=r"(r[0]), "=r"(r[1]), "=r"(r[2]), "=r"(r[3]) : "r"(a));
}
__device__ __forceinline__ void ldsm4t(uint32_t* r, uint32_t a) {
    asm volatile("ldmatrix.sync.aligned.m8n8.x4.trans.shared.b16 {%0,%1,%2,%3}, [%4];"
                 : "=r"(r[0]), "=r"(r[1]), "=r"(r[2]), "=r"(r[3]) : "r"(a));
}
__device__ __forceinline__ void mma16816(float* c, const uint32_t* a, const uint32_t* b) {
    asm volatile(
        "mma.sync.aligned.m16n8k16.row.col.f32.bf16.bf16.f32 "
        "{%0,%1,%2,%3}, {%4,%5,%6,%7}, {%8,%9}, {%0,%1,%2,%3};"
        : "+f"(c[0]), "+f"(c[1]), "+f"(c[2]), "+f"(c[3])
        : "r"(a[0]), "r"(a[1]), "r"(a[2]), "r"(a[3]), "r"(b[0]), "r"(b[1]));
}
__device__ __forceinline__ void cpa16(uint32_t dst, const void* src, bool pred) {
    int sz = pred ? 16 : 0;
    asm volatile("cp.async.cg.shared.global [%0], [%1], 16, %2;"
                 :: "r"(dst), "l"(src), "r"(sz) : "memory");
}
#define CP_COMMIT() asm volatile("cp.async.commit_group;" ::: "memory")
#define CP_WAIT0()  asm volatile("cp.async.wait_group 0;" ::: "memory")
#define CP_WAIT1()  asm volatile("cp.async.wait_group 1;" ::: "memory")

__device__ __forceinline__ void cvt_hilo(float4 v, uint2& h, uint2& l) {
    __nv_bfloat162 h0 = __floats2bfloat162_rn(v.x, v.y);
    __nv_bfloat162 h1 = __floats2bfloat162_rn(v.z, v.w);
    float2 f0 = __bfloat1622float2(h0), f1 = __bfloat1622float2(h1);
    __nv_bfloat162 l0 = __floats2bfloat162_rn(v.x - f0.x, v.y - f0.y);
    __nv_bfloat162 l1 = __floats2bfloat162_rn(v.z - f1.x, v.w - f1.y);
    h.x = *(uint32_t*)&h0; h.y = *(uint32_t*)&h1;
    l.x = *(uint32_t*)&l0; l.y = *(uint32_t*)&l1;
}

// ---------------- merged weight conversion ----------------
struct CvtSeg { const float4* src; uint2* hi; uint2* lo; long n4; };
__global__ void cvtw_all_k(CvtSeg s0, CvtSeg s1, CvtSeg s2, CvtSeg s3) {
    long base = (long)blockIdx.x * blockDim.x + threadIdx.x;
    long stride = (long)gridDim.x * blockDim.x;
    CvtSeg segs[4] = {s0, s1, s2, s3};
#pragma unroll
    for (int si = 0; si < 4; si++) {
        CvtSeg s = segs[si];
        for (long i = base; i < s.n4; i += stride) {
            uint2 h, l;
            cvt_hilo(s.src[i], h, l);
            s.hi[i] = h; s.lo[i] = l;
        }
    }
}

// ============ HMMA GEMM (R8 config): 128x128 tile, BK=64, 3-stage ============
#define BM 128
#define BN 128
#define BK 64
#define A_STRIDE 144
#define B_STRIDE 272
#define OFF_AHI 0
#define OFF_ALO 18432
#define OFF_BHI 36864
#define OFF_BLO 54272
#define STG     71680
#define NSTAGE  3
#define SMEMSZ  (NSTAGE * STG)

template <int MODE>
__global__ __launch_bounds__(256, 1) void gemm_bf(
    const __nv_bfloat16* __restrict__ Ah, const __nv_bfloat16* __restrict__ Al,
    const __nv_bfloat16* __restrict__ Bh, const __nv_bfloat16* __restrict__ Bl,
    const float* __restrict__ bias, float* __restrict__ C,
    __nv_bfloat16* __restrict__ Chi, __nv_bfloat16* __restrict__ Clo,
    int M, int N, int K,
    const int* __restrict__ rowlist, const float* __restrict__ roww,
    const int* __restrict__ cntp, float* __restrict__ X,
    long zA, long zB, long zBias, long zC) {
    extern __shared__ char smem[];
    int tid = threadIdx.x, wid = tid >> 5, lane = tid & 31;

    int ez = blockIdx.z;
    if (ez) {
        Ah += (size_t)ez * zA; Al += (size_t)ez * zA;
        Bh += (size_t)ez * zB; Bl += (size_t)ez * zB;
        bias += (size_t)ez * zBias;
        Chi += (size_t)ez * zC; Clo += (size_t)ez * zC;
        rowlist += ez * SEQ; roww += ez * SEQ; cntp += ez;
    }
    int Meff = M;
    if (MODE == 2 || MODE == 3) Meff = *cntp;
    int row0 = blockIdx.x * BM;
    if ((MODE == 2 || MODE == 3) && row0 >= Meff) return;
    int n0 = blockIdx.y * BN;

    int asrc[4];
#pragma unroll
    for (int i = 0; i < 4; i++) {
        int rg = row0 + (tid >> 3) + 32 * i;
        asrc[i] = (rg < Meff) ? ((MODE == 2) ? rowlist[rg] : rg) : -1;
    }
    int ac16 = tid & 7;

    const int NC = K / BK;
    uint32_t sb = smem_u32(smem);
    int wm = wid & 1, wn = wid >> 1;

    float acc[4][4][4];
#pragma unroll
    for (int a = 0; a < 4; a++)
#pragma unroll
        for (int b = 0; b < 4; b++)
#pragma unroll
            for (int c = 0; c < 4; c++) acc[a][b][c] = 0.f;

    auto issue = [&](int c, int s) {
        uint32_t stg = sb + (uint32_t)s * STG;
        int k0 = c * BK;
#pragma unroll
        for (int i = 0; i < 4; i++) {
            int row = (tid >> 3) + 32 * i;
            bool ok = asrc[i] >= 0;
            size_t go = ok ? ((size_t)asrc[i] * K + k0 + ac16 * 8) : 0;
            uint32_t so = (uint32_t)row * A_STRIDE + (uint32_t)ac16 * 16;
            cpa16(stg + OFF_AHI + so, Ah + go, ok);
            cpa16(stg + OFF_ALO + so, Al + go, ok);
        }
#pragma unroll
        for (int i = 0; i < 4; i++) {
            int idx = tid + 256 * i;
            int k = idx >> 4, c16 = idx & 15;
            int ng = n0 + c16 * 8;
            bool ok = ng < N;
            size_t go = ok ? ((size_t)(k0 + k) * N + ng) : 0;
            uint32_t so = (uint32_t)k * B_STRIDE + (uint32_t)c16 * 16;
            cpa16(stg + OFF_BHI + so, Bh + go, ok);
            cpa16(stg + OFF_BLO + so, Bl + go, ok);
        }
    };

    auto compute = [&](uint32_t stg) {
#pragma unroll
        for (int kk = 0; kk < 4; kk++) {
            uint32_t ah[4][4], al[4][4], bb[2][4];
#pragma unroll
            for (int mi = 0; mi < 4; mi++) {
                uint32_t off = (uint32_t)(wm * 64 + mi * 16 + (lane & 15)) * A_STRIDE
                             + kk * 32 + ((lane >> 4) << 4);
                ldsm4(ah[mi], stg + OFF_AHI + off);
                ldsm4(al[mi], stg + OFF_ALO + off);
            }
#pragma unroll
            for (int bi = 0; bi < 2; bi++) {
                uint32_t off = (uint32_t)(kk * 16 + (lane & 15)) * B_STRIDE
                             + (uint32_t)(wn * 32 + bi * 16 + ((lane >> 4) << 3)) * 2;
                ldsm4t(bb[bi], stg + OFF_BHI + off);
            }
#pragma unroll
            for (int mi = 0; mi < 4; mi++)
#pragma unroll
                for (int bi = 0; bi < 2; bi++) {
                    mma16816(acc[mi][bi * 2],     ah[mi], &bb[bi][0]);
                    mma16816(acc[mi][bi * 2 + 1], ah[mi], &bb[bi][2]);
                    mma16816(acc[mi][bi * 2],     al[mi], &bb[bi][0]);
                    mma16816(acc[mi][bi * 2 + 1], al[mi], &bb[bi][2]);
                }
#pragma unroll
            for (int bi = 0; bi < 2; bi++) {
                uint32_t off = (uint32_t)(kk * 16 + (lane & 15)) * B_STRIDE
                             + (uint32_t)(wn * 32 + bi * 16 + ((lane >> 4) << 3)) * 2;
                ldsm4t(bb[bi], stg + OFF_BLO + off);
            }
#pragma unroll
            for (int mi = 0; mi < 4; mi++)
#pragma unroll
                for (int bi = 0; bi < 2; bi++) {
                    mma16816(acc[mi][bi * 2],     ah[mi], &bb[bi][0]);
                    mma16816(acc[mi][bi * 2 + 1], ah[mi], &bb[bi][2]);
                }
        }
    };

    issue(0, 0); CP_COMMIT();
    if (NC > 1) { issue(1, 1); CP_COMMIT(); }

    for (int c = 0; c < NC; c++) {
        if (c + 1 < NC) CP_WAIT1(); else CP_WAIT0();
        __syncthreads();
        compute(sb + (uint32_t)(c % NSTAGE) * STG);
        if (c + 2 < NC) { issue(c + 2, (c + 2) % NSTAGE); CP_COMMIT(); }
    }

#pragma unroll
    for (int mi = 0; mi < 4; mi++) {
#pragma unroll
        for (int nj = 0; nj < 4; nj++) {
            int rbase = row0 + wm * 64 + mi * 16 + (lane >> 2);
            int c = n0 + wn * 32 + nj * 8 + (lane & 3) * 2;
#pragma unroll
            for (int hf = 0; hf < 2; hf++) {
                int r = rbase + hf * 8;
                if (r >= Meff) continue;
                float v0 = acc[mi][nj][hf * 2], v1 = acc[mi][nj][hf * 2 + 1];
                if (MODE == 0) {
                    if (c < N)     C[(size_t)r * N + c]     = v0 + bias[c];
                    if (c + 1 < N) C[(size_t)r * N + c + 1] = v1 + bias[c + 1];
                } else if (MODE == 1) {
                    if (c < N)     X[(size_t)r * N + c]     += v0 + bias[c];
                    if (c + 1 < N) X[(size_t)r * N + c + 1] += v1 + bias[c + 1];
                } else if (MODE == 2) {
                    if (c < N) {
                        float h0 = v0 + bias[c];
                        float h1 = v1 + bias[c + 1];
                        float glu = fminf(h0, LIMITF);
                        float lin = fminf(fmaxf(h1, -LIMITF), LIMITF);
                        float a = glu * (1.0f / (1.0f + expf(-ALPHAF * glu))) * (lin + 1.0f);
                        __nv_bfloat16 hb = __float2bfloat16(a);
                        size_t o = (size_t)r * INTER + (c >> 1);
                        Chi[o] = hb;
                        Clo[o] = __float2bfloat16(a - __bfloat162float(hb));
                    }
                } else {
                    int tk = rowlist[r];
                    float w = roww[r];
                    if (c < N)     atomicAdd(&X[(size_t)tk * DIMV + c],     w * (v0 + bias[c]));
                    if (c + 1 < N) atomicAdd(&X[(size_t)tk * DIMV + c + 1], w * (v1 + bias[c + 1]));
                }
            }
        }
    }
}

// ---------------- YaRN ----------------
__global__ void yarn_k(float* __restrict__ cosT, float* __restrict__ sinT) {
    int pos = blockIdx.x, d = threadIdx.x;
    double freq = pow(150000.0, (double)d / 32.0);
    double low  = 32.0 * log(4096.0 / (32.0 * 2.0 * M_PI)) / log(150000.0);
    double high = 32.0 * log(4096.0 / (2.0 * M_PI)) / log(150000.0);
    double ramp = ((double)d - low) / (high - low);
    double mm = 1.0 - fmin(fmax(ramp, 0.0), 1.0);
    double inv = (1.0 / (32.0 * freq)) * (1.0 - mm) + (1.0 / freq) * mm;
    double conc = 0.1 * log(32.0) + 1.0;
    double fr = (double)pos * inv;
    cosT[pos * 32 + d] = (float)(cos(fr) * conc);
    sinT[pos * 32 + d] = (float)(sin(fr) * conc);
}

// ---------------- RMSNorm ----------------
__global__ void rmsnorm_k(const float* __restrict__ x, const float* __restrict__ w,
                          float* __restrict__ o32, __nv_bfloat16* __restrict__ oh,
                          __nv_bfloat16* __restrict__ ol) {
    int t = blockIdx.x, tid = threadIdx.x;
    __shared__ float red[256];
    const float* xr = x + (size_t)t * DIMV;
    float s = 0.f;
    for (int i = tid; i < DIMV; i += 256) { float v = xr[i]; s += v * v; }
    red[tid] = s; __syncthreads();
    for (int off = 128; off > 0; off >>= 1) {
        if (tid < off) red[tid] += red[tid + off];
        __syncthreads();
    }
    float inv = 1.0f / sqrtf(red[0] / (float)DIMV + 1e-5f);
    size_t base = (size_t)t * DIMV;
    for (int i = tid; i < DIMV; i += 256) {
        float v = xr[i] * inv * w[i];
        o32[base + i] = v;
        __nv_bfloat16 h = __float2bfloat16(v);
        oh[base + i] = h;
        ol[base + i] = __float2bfloat16(v - __bfloat162float(h));
    }
}

// ---------------- RoPE ----------------
__global__ void rope_k(float* __restrict__ qkv, const float* __restrict__ cosT,
                       const float* __restrict__ sinT) {
    int pos = blockIdx.x;
    for (int idx = threadIdx.x; idx < (NH + NKV) * 32; idx += 256) {
        int hh = idx >> 5, d = idx & 31;
        int col = (hh < NH) ? hh * HD : QD + (hh - NH) * HD;
        float c = cosT[pos * 32 + d], s = sinT[pos * 32 + d];
        float* p = qkv + (size_t)pos * QKVD + col;
        float x1 = p[d], x2 = p[d + 32];
        p[d] = x1 * c - x2 * s;
        p[d + 32] = x2 * c + x1 * s;
    }
}

// ---------------- Attention: MMA, 64 queries x 1 head per block ----------------
#define AQ 64
#define AO_QH  0
#define AO_QL  9216
#define AO_KVH 18432
#define AO_KVL 27648
#define AO_PH  36864
#define AO_PL  46080
#define AO_PS  55296              // float[64][68]
#define AO_SC  72704              // scale[64], m[64], l[64]
#define ATTN_SMEM (72704 + 64 * 12)

__global__ __launch_bounds__(128) void attn_k(const float* __restrict__ qkv,
                                              const float* __restrict__ sinks,
                                              __nv_bfloat16* __restrict__ outh,
                                              __nv_bfloat16* __restrict__ outl,
                                              int window) {
    extern __shared__ __align__(16) char asm_[];
    char* q_h = asm_ + AO_QH;
    char* q_l = asm_ + AO_QL;
    char* kv_h = asm_ + AO_KVH;
    char* kv_l = asm_ + AO_KVL;
    char* p_hm = asm_ + AO_PH;
    char* p_lm = asm_ + AO_PL;
    float (*p_s)[68] = (float(*)[68])(asm_ + AO_PS);
    float* scale_s = (float*)(asm_ + AO_SC);
    float* m_s = scale_s + 64;
    float* l_s = scale_s + 128;

    int qb = blockIdx.x, h = blockIdx.y;
    int q0 = qb * AQ, kvh = h >> 3;
    int tid = threadIdx.x, wid = tid >> 5, lane = tid & 31;

    for (int i = tid; i < AQ * 16; i += 128) {
        int row = i >> 4, c = (i & 15) * 4;
        float4 v = *(const float4*)&qkv[(size_t)(q0 + row) * QKVD + h * HD + c];
        uint2 hh, ll; cvt_hilo(v, hh, ll);
        *(uint2*)(q_h + row * 144 + c * 2) = hh;
        *(uint2*)(q_l + row * 144 + c * 2) = ll;
    }
    if (tid < AQ) { m_s[tid] = sinks[h]; l_s[tid] = 1.0f; }

    float o_acc[4][2][4];
#pragma unroll
    for (int a = 0; a < 4; a++)
#pragma unroll
        for (int b = 0; b < 2; b++)
#pragma unroll
            for (int c = 0; c < 4; c++) o_acc[a][b][c] = 0.f;

    int jlo = 0;
    if (window > 0) { jlo = q0 - window + 1; if (jlo < 0) jlo = 0; }
    int kcol = QD + kvh * HD, vcol = QD + KDOFF + kvh * HD;
    int srow = tid >> 1, ssub = tid & 1;

    uint32_t qh_b = smem_u32(q_h), ql_b = smem_u32(q_l);
    uint32_t kvh_b = smem_u32(kv_h), kvl_b = smem_u32(kv_l);
    uint32_t ph_b = smem_u32(p_hm), pl_b = smem_u32(p_lm);

    for (int t0 = (jlo >> 6) << 6; t0 <= q0 + AQ - 1; t0 += 64) {
        __syncthreads();
        for (int i = tid; i < 64 * 16; i += 128) {
            int row = i >> 4, c = (i & 15) * 4;
            float4 v = *(const float4*)&qkv[(size_t)(t0 + row) * QKVD + kcol + c];
            uint2 hh, ll; cvt_hilo(v, hh, ll);
            *(uint2*)(kv_h + row * 144 + c * 2) = hh;
            *(uint2*)(kv_l + row * 144 + c * 2) = ll;
        }
        __syncthreads();

        // S = Q K^T
        float s_acc[4][2][4];
#pragma unroll
        for (int a = 0; a < 4; a++)
#pragma unroll
            for (int b = 0; b < 2; b++)
#pragma unroll
                for (int c = 0; c < 4; c++) s_acc[a][b][c] = 0.f;
#pragma unroll
        for (int kk = 0; kk < 4; kk++) {
            uint32_t qa_h[4][4], qa_l[4][4], kb_h[4], kb_l[4];
#pragma unroll
            for (int mi = 0; mi < 4; mi++) {
                uint32_t off = (uint32_t)(mi * 16 + (lane & 15)) * 144 + kk * 32 + ((lane >> 4) << 4);
                ldsm4(qa_h[mi], qh_b + off);
                ldsm4(qa_l[mi], ql_b + off);
            }
            {
                uint32_t off = (uint32_t)(wid * 16 + (lane & 15)) * 144 + kk * 32 + ((lane >> 4) << 4);
                ldsm4(kb_h, kvh_b + off);
                ldsm4(kb_l, kvl_b + off);
            }
#pragma unroll
            for (int mi = 0; mi < 4; mi++)
#pragma unroll
                for (int nj = 0; nj < 2; nj++) {
                    uint32_t bh2[2] = {kb_h[nj], kb_h[nj + 2]};
                    uint32_t bl2[2] = {kb_l[nj], kb_l[nj + 2]};
                    mma16816(s_acc[mi][nj], qa_h[mi], bh2);
                    mma16816(s_acc[mi][nj], qa_l[mi], bh2);
                    mma16816(s_acc[mi][nj], qa_h[mi], bl2);
                }
        }
#pragma unroll
        for (int mi = 0; mi < 4; mi++)
#pragma unroll
            for (int nj = 0; nj < 2; nj++)
#pragma unroll
                for (int hf = 0; hf < 2; hf++) {
                    int r = mi * 16 + (lane >> 2) + hf * 8;
                    int cc = wid * 16 + nj * 8 + (lane & 3) * 2;
                    int ii = q0 + r;
#pragma unroll
                    for (int e = 0; e < 2; e++) {
                        int jj = t0 + cc + e;
                        bool ok = (jj <= ii) && (window == 0 || (ii - jj) < window);
                        p_s[r][cc + e] = ok ? s_acc[mi][nj][hf * 2 + e] * SM_SCALE : -1e30f;
                    }
                }
        __syncthreads();

        // online softmax: 2 threads/row, 32 cols each
        {
            float mloc = -1e30f;
#pragma unroll
            for (int j = 0; j < 32; j++) mloc = fmaxf(mloc, p_s[srow][ssub * 32 + j]);
            mloc = fmaxf(mloc, __shfl_xor_sync(0xffffffffu, mloc, 1));
            float mold = m_s[srow];
            float mn = fmaxf(mold, mloc);
            float sum = 0.f;
#pragma unroll
            for (int j = 0; j < 32; j++) {
                float e = __expf(p_s[srow][ssub * 32 + j] - mn);
                p_s[srow][ssub * 32 + j] = e;
                sum += e;
            }
            sum += __shfl_xor_sync(0xffffffffu, sum, 1);
            if (ssub == 0) {
                float rs = __expf(mold - mn);
                l_s[srow] = l_s[srow] * rs + sum;
                m_s[srow] = mn;
                scale_s[srow] = rs;
            }
        }
        __syncthreads();

#pragma unroll
        for (int mi = 0; mi < 4; mi++)
#pragma unroll
            for (int hf = 0; hf < 2; hf++) {
                int r = mi * 16 + (lane >> 2) + hf * 8;
                float s = scale_s[r];
#pragma unroll
                for (int nj = 0; nj < 2; nj++) {
                    o_acc[mi][nj][hf * 2]     *= s;
                    o_acc[mi][nj][hf * 2 + 1] *= s;
                }
            }
        // P -> bf16 hi/lo
#pragma unroll
        for (int j = 0; j < 32; j += 2) {
            int c = ssub * 32 + j;
            float v0 = p_s[srow][c], v1 = p_s[srow][c + 1];
            __nv_bfloat162 hh = __floats2bfloat162_rn(v0, v1);
            float2 f = __bfloat1622float2(hh);
            __nv_bfloat162 ll = __floats2bfloat162_rn(v0 - f.x, v1 - f.y);
            *(uint32_t*)(p_hm + srow * 144 + c * 2) = *(uint32_t*)&hh;
            *(uint32_t*)(p_lm + srow * 144 + c * 2) = *(uint32_t*)&ll;
        }
        // V tile
        for (int i = tid; i < 64 * 16; i += 128) {
            int row = i >> 4, c = (i & 15) * 4;
            float4 v = *(const float4*)&qkv[(size_t)(t0 + row) * QKVD + vcol + c];
            uint2 hh, ll; cvt_hilo(v, hh, ll);
            *(uint2*)(kv_h + row * 144 + c * 2) = hh;
            *(uint2*)(kv_l + row * 144 + c * 2) = ll;
        }
        __syncthreads();

        // O += P V
#pragma unroll
        for (int kk = 0; kk < 4; kk++) {
            uint32_t pa_h[4][4], pa_l[4][4], vb_h[4], vb_l[4];
#pragma unroll
            for (int mi = 0; mi < 4; mi++) {
                uint32_t off = (uint32_t)(mi * 16 + (lane & 15)) * 144 + kk * 32 + ((lane >> 4) << 4);
                ldsm4(pa_h[mi], ph_b + off);
                ldsm4(pa_l[mi], pl_b + off);
            }
            {
                uint32_t off = (uint32_t)(kk * 16 + (lane & 15)) * 144
                             + (uint32_t)(wid * 16 + ((lane >> 4) << 3)) * 2;
                ldsm4t(vb_h, kvh_b + off);
                ldsm4t(vb_l, kvl_b + off);
            }
#pragma unroll
            for (int mi = 0; mi < 4; mi++)
#pragma unroll
                for (int nj = 0; nj < 2; nj++) {
                    mma16816(o_acc[mi][nj], pa_h[mi], &vb_h[nj * 2]);
                    mma16816(o_acc[mi][nj], pa_l[mi], &vb_h[nj * 2]);
                    mma16816(o_acc[mi][nj], pa_h[mi], &vb_l[nj * 2]);
                }
        }
    }
    __syncthreads();
    if (tid < AQ) scale_s[tid] = 1.0f / l_s[tid];
    __syncthreads();
#pragma unroll
    for (int mi = 0; mi < 4; mi++)
#pragma unroll
        for (int nj = 0; nj < 2; nj++)
#pragma unroll
            for (int hf = 0; hf < 2; hf++) {
                int r = mi * 16 + (lane >> 2) + hf * 8;
                float li = scale_s[r];
                int cc = wid * 16 + nj * 8 + (lane & 3) * 2;
#pragma unroll
                for (int e = 0; e < 2; e++) {
                    float v = o_acc[mi][nj][hf * 2 + e] * li;
                    size_t o = (size_t)(q0 + r) * QD + h * HD + cc + e;
                    __nv_bfloat16 hb = __float2bfloat16(v);
                    outh[o] = hb;
                    outl[o] = __float2bfloat16(v - __bfloat162float(hb));
                }
            }
}

// ---------------- gate + routing ----------------
__global__ void gate_k(const float* __restrict__ t, const float* __restrict__ gw,
                       const float* __restrict__ gb, int* __restrict__ sel,
                       float* __restrict__ selw) {
    int tk = blockIdx.x, tid = threadIdx.x;
    __shared__ float red[4][128];
    float p[4] = {0.f, 0.f, 0.f, 0.f};
    const float* tr = t + (size_t)tk * DIMV;
    for (int k = tid; k < DIMV; k += 128) {
        float v = tr[k];
#pragma unroll
        for (int e = 0; e < 4; e++) p[e] += v * gw[k * 4 + e];
    }
#pragma unroll
    for (int e = 0; e < 4; e++) red[e][tid] = p[e];
    __syncthreads();
    for (int off = 64; off > 0; off >>= 1) {
        if (tid < off)
#pragma unroll
            for (int e = 0; e < 4; e++) red[e][tid] += red[e][tid + off];
        __syncthreads();
    }
    if (tid == 0) {
        float v[4];
#pragma unroll
        for (int e = 0; e < 4; e++) v[e] = red[e][0] + gb[e];
        int i0 = 0;
        for (int e = 1; e < 4; e++) if (v[e] > v[i0]) i0 = e;
        int i1 = (i0 == 0) ? 1 : 0;
        for (int e = 0; e < 4; e++) if (e != i0 && v[e] > v[i1]) i1 = e;
        float ex = expf(v[i1] - v[i0]);
        float den = 1.0f + ex;
        sel[tk * 2] = i0; sel[tk * 2 + 1] = i1;
        selw[tk * 2] = 1.0f / den; selw[tk * 2 + 1] = ex / den;
    }
}

__global__ void build_lists_k(const int* __restrict__ sel, const float* __restrict__ selw,
                              int* __restrict__ list, float* __restrict__ wgt,
                              int* __restrict__ cnt) {
    int w = threadIdx.x >> 5, lane = threadIdx.x & 31;
    if (w >= NEXP) return;
    int e = w, c = 0;
    for (int base = 0; base < SEQ; base += 32) {
        int tk = base + lane;
        int s0 = sel[tk * 2], s1 = sel[tk * 2 + 1];
        bool f = (s0 == e) || (s1 == e);
        float wv = (s0 == e) ? selw[tk * 2] : selw[tk * 2 + 1];
        unsigned msk = __ballot_sync(0xffffffffu, f);
        if (f) {
            int pos = c + __popc(msk & ((1u << lane) - 1u));
            list[e * SEQ + pos] = tk;
            wgt[e * SEQ + pos]  = wv;
        }
        c += __popc(msk);
    }
    if (lane == 0) cnt[e] = c;
}

// ---------------- host ----------------
extern "C" void kernel_launch(void* const* d_in, const int* in_sizes, int n_in,
                              void* d_out, int out_size) {
    const float* x_in  = (const float*)d_in[0];
    const float* rms1w = (const float*)d_in[1];
    const float* qkvw  = (const float*)d_in[2];
    const float* qkvb  = (const float*)d_in[3];
    const float* outw  = (const float*)d_in[4];
    const float* outb  = (const float*)d_in[5];
    const float* sinks = (const float*)d_in[6];
    const float* rms2w = (const float*)d_in[7];
    const float* gatew = (const float*)d_in[8];
    const float* gateb = (const float*)d_in[9];
    const float* w1    = (const float*)d_in[10];
    const float* b1    = (const float*)d_in[11];
    const float* w2    = (const float*)d_in[12];
    const float* b2    = (const float*)d_in[13];

    float *t32, *qkv, *cosT, *sinT, *selw, *wgt;
    __nv_bfloat16 *th, *tl, *ah, *al, *acth, *actl;
    __nv_bfloat16 *qwh, *qwl, *owh, *owl, *w1h, *w1l, *w2h, *w2l;
    int *sel, *list, *cnt;
    cudaGetSymbolAddress((void**)&t32, g_t32);
    cudaGetSymbolAddress((void**)&th, g_th);
    cudaGetSymbolAddress((void**)&tl, g_tl);
    cudaGetSymbolAddress((void**)&qkv, g_qkv);
    cudaGetSymbolAddress((void**)&ah, g_ah);
    cudaGetSymbolAddress((void**)&al, g_al);
    cudaGetSymbolAddress((void**)&acth, g_acth);
    cudaGetSymbolAddress((void**)&actl, g_actl);
    cudaGetSymbolAddress((void**)&cosT, g_cos);
    cudaGetSymbolAddress((void**)&sinT, g_sin);
    cudaGetSymbolAddress((void**)&sel, g_sel);
    cudaGetSymbolAddress((void**)&selw, g_selw);
    cudaGetSymbolAddress((void**)&list, g_list);
    cudaGetSymbolAddress((void**)&wgt, g_wgt);
    cudaGetSymbolAddress((void**)&cnt, g_cnt);
    cudaGetSymbolAddress((void**)&qwh, g_qkvw_h);
    cudaGetSymbolAddress((void**)&qwl, g_qkvw_l);
    cudaGetSymbolAddress((void**)&owh, g_outw_h);
    cudaGetSymbolAddress((void**)&owl, g_outw_l);
    cudaGetSymbolAddress((void**)&w1h, g_w1_h);
    cudaGetSymbolAddress((void**)&w1l, g_w1_l);
    cudaGetSymbolAddress((void**)&w2h, g_w2_h);
    cudaGetSymbolAddress((void**)&w2l, g_w2_l);

    cudaFuncSetAttribute(gemm_bf<0>, cudaFuncAttributeMaxDynamicSharedMemorySize, SMEMSZ);
    cudaFuncSetAttribute(gemm_bf<1>, cudaFuncAttributeMaxDynamicSharedMemorySize, SMEMSZ);
    cudaFuncSetAttribute(gemm_bf<2>, cudaFuncAttributeMaxDynamicSharedMemorySize, SMEMSZ);
    cudaFuncSetAttribute(gemm_bf<3>, cudaFuncAttributeMaxDynamicSharedMemorySize, SMEMSZ);
    cudaFuncSetAttribute(attn_k, cudaFuncAttributeMaxDynamicSharedMemorySize, ATTN_SMEM);

    float* X = (float*)d_out;
    cudaMemcpyAsync(X, x_in, sizeof(float) * SEQ * DIMV, cudaMemcpyDeviceToDevice);
    yarn_k<<<SEQ, 32>>>(cosT, sinT);

    CvtSeg s0 = {(const float4*)qkvw, (uint2*)qwh, (uint2*)qwl, NQKVW / 4};
    CvtSeg s1 = {(const float4*)outw, (uint2*)owh, (uint2*)owl, NOUTW / 4};
    CvtSeg s2 = {(const float4*)w1,   (uint2*)w1h, (uint2*)w1l, NW1 / 4};
    CvtSeg s3 = {(const float4*)w2,   (uint2*)w2h, (uint2*)w2l, NW2 / 4};
    cvtw_all_k<<<4736, 256>>>(s0, s1, s2, s3);

    for (int layer = 0; layer < 2; layer++) {
        rmsnorm_k<<<SEQ, 256>>>(X, rms1w + (size_t)layer * DIMV, t32, th, tl);
        gemm_bf<0><<<dim3(SEQ / 128, QKVD / 128, 1), 256, SMEMSZ>>>(
            th, tl, qwh + (size_t)layer * DIMV * QKVD, qwl + (size_t)layer * DIMV * QKVD,
            qkvb + (size_t)layer * QKVD, qkv, nullptr, nullptr,
            SEQ, QKVD, DIMV, nullptr, nullptr, nullptr, nullptr, 0, 0, 0, 0);
        rope_k<<<SEQ, 256>>>(qkv, cosT, sinT);
        attn_k<<<dim3(SEQ / AQ, NH), 128, ATTN_SMEM>>>(qkv, sinks + (size_t)layer * NH, ah, al,
                                                       (layer % 2 == 0) ? 128 : 0);
        gemm_bf<1><<<dim3(SEQ / 128, (DIMV + 127) / 128, 1), 256, SMEMSZ>>>(
            ah, al, owh + (size_t)layer * QD * DIMV, owl + (size_t)layer * QD * DIMV,
            outb + (size_t)layer * DIMV, nullptr, nullptr, nullptr,
            SEQ, DIMV, QD, nullptr, nullptr, nullptr, X, 0, 0, 0, 0);

        rmsnorm_k<<<SEQ, 256>>>(X, rms2w + (size_t)layer * DIMV, t32, th, tl);
        gate_k<<<SEQ, 128>>>(t32, gatew + (size_t)layer * DIMV * NEXP,
                             gateb + (size_t)layer * NEXP, sel, selw);
        build_lists_k<<<1, 128>>>(sel, selw, list, wgt, cnt);

        gemm_bf<2><<<dim3(SEQ / 128, (2 * INTER) / 128, NEXP), 256, SMEMSZ>>>(
            th, tl,
            w1h + (size_t)layer * NEXP * DIMV * 2 * INTER,
            w1l + (size_t)layer * NEXP * DIMV * 2 * INTER,
            b1 + (size_t)layer * NEXP * 2 * INTER,
            nullptr, acth, actl,
            0, 2 * INTER, DIMV, list, wgt, cnt, nullptr,
            0, (long)DIMV * 2 * INTER, 2 * INTER, (long)SEQ * INTER);

        gemm_bf<3><<<dim3(SEQ / 128, (DIMV + 127) / 128, NEXP), 256, SMEMSZ>>>(
            acth, actl,
            w2h + (size_t)layer * NEXP * INTER * DIMV,
            w2l + (size_t)layer * NEXP * INTER * DIMV,
            b2 + (size_t)layer * NEXP * DIMV, nullptr, nullptr, nullptr,
            0, DIMV, INTER, list, wgt, cnt, X,
            (long)SEQ * INTER, (long)INTER * DIMV, DIMV, 0);
    }
    (void)in_sizes; (void)n_in; (void)out_size;
}

// round 17
// speedup vs baseline: 1.0729x; 1.0729x over previous
#include <cuda_runtime.h>
#include <cuda_bf16.h>
#include <math.h>
#include <stdint.h>

#define DIMV 2880
#define SEQ  1024
#define NH   64
#define NKV  8
#define HD   64
#define QKVD 5120
#define QD   4096
#define KDOFF 512
#define INTER 2880
#define NEXP 4
#define LIMITF 7.0f
#define ALPHAF 1.702f
#define SM_SCALE 0.125f

#define NQKVW (2L * DIMV * QKVD)
#define NOUTW (2L * QD * DIMV)
#define NW1   (2L * NEXP * DIMV * 2 * INTER)
#define NW2   (2L * NEXP * INTER * DIMV)

// ---- scratch ----
__device__ __align__(16) float g_t32[SEQ * DIMV];
__device__ __align__(16) __nv_bfloat16 g_th[SEQ * DIMV];
__device__ __align__(16) __nv_bfloat16 g_tl[SEQ * DIMV];
__device__ __align__(16) float g_qkv[SEQ * QKVD];
__device__ __align__(16) float g_qkvp[3L * SEQ * QKVD];
__device__ __align__(16) float g_outp[2L * SEQ * DIMV];
__device__ __align__(16) __nv_bfloat16 g_ah[SEQ * QD];
__device__ __align__(16) __nv_bfloat16 g_al[SEQ * QD];
__device__ __align__(16) __nv_bfloat16 g_acth[NEXP * SEQ * INTER];
__device__ __align__(16) __nv_bfloat16 g_actl[NEXP * SEQ * INTER];
__device__ __align__(16) float g_cos[SEQ * 32];
__device__ __align__(16) float g_sin[SEQ * 32];
__device__ int   g_sel[SEQ * 2];
__device__ float g_selw[SEQ * 2];
__device__ int   g_list[NEXP * SEQ];
__device__ float g_wgt[NEXP * SEQ];
__device__ int   g_cnt[NEXP];
__device__ __align__(16) __nv_bfloat16 g_qkvw_h[NQKVW];
__device__ __align__(16) __nv_bfloat16 g_qkvw_l[NQKVW];
__device__ __align__(16) __nv_bfloat16 g_outw_h[NOUTW];
__device__ __align__(16) __nv_bfloat16 g_outw_l[NOUTW];
__device__ __align__(16) __nv_bfloat16 g_w1_h[NW1];
__device__ __align__(16) __nv_bfloat16 g_w1_l[NW1];
__device__ __align__(16) __nv_bfloat16 g_w2_h[NW2];
__device__ __align__(16) __nv_bfloat16 g_w2_l[NW2];

// ---------------- helpers ----------------
__device__ __forceinline__ uint32_t smem_u32(const void* p) {
    uint32_t a;
    asm("{ .reg .u64 t; cvta.to.shared.u64 t, %1; cvt.u32.u64 %0, t; }" : "=r"(a) : "l"(p));
    return a;
}
__device__ __forceinline__ void ldsm4(uint32_t* r, uint32_t a) {
    asm volatile("ldmatrix.sync.aligned.m8n8.x4.shared.b16 {%0,%1,%2,%3}, [%4];"
                 : "=r"(r[0]), "=r"(r[1]), "=r"(r[2]), "=r"(r[3]) : "r"(a));
}
__device__ __forceinline__ void ldsm4t(uint32_t* r, uint32_t a) {
    asm volatile("ldmatrix.sync.aligned.m8n8.x4.trans.shared.b16 {%0,%1,%2,%3}, [%4];"
                 : "=r"(r[0]), "=r"(r[1]), "=r"(r[2]), "=r"(r[3]) : "r"(a));
}
__device__ __forceinline__ void mma16816(float* c, const uint32_t* a, const uint32_t* b) {
    asm volatile(
        "mma.sync.aligned.m16n8k16.row.col.f32.bf16.bf16.f32 "
        "{%0,%1,%2,%3}, {%4,%5,%6,%7}, {%8,%9}, {%0,%1,%2,%3};"
        : "+f"(c[0]), "+f"(c[1]), "+f"(c[2]), "+f"(c[3])
        : "r"(a[0]), "r"(a[1]), "r"(a[2]), "r"(a[3]), "r"(b[0]), "r"(b[1]));
}
__device__ __forceinline__ void cpa16(uint32_t dst, const void* src, bool pred) {
    int sz = pred ? 16 : 0;
    asm volatile("cp.async.cg.shared.global [%0], [%1], 16, %2;"
                 :: "r"(dst), "l"(src), "r"(sz) : "memory");
}
#define CP_COMMIT() asm volatile("cp.async.commit_group;" ::: "memory")
#define CP_WAIT0()  asm volatile("cp.async.wait_group 0;" ::: "memory")
#define CP_WAIT1()  asm volatile("cp.async.wait_group 1;" ::: "memory")

__device__ __forceinline__ void cvt_hilo(float4 v, uint2& h, uint2& l) {
    __nv_bfloat162 h0 = __floats2bfloat162_rn(v.x, v.y);
    __nv_bfloat162 h1 = __floats2bfloat162_rn(v.z, v.w);
    float2 f0 = __bfloat1622float2(h0), f1 = __bfloat1622float2(h1);
    __nv_bfloat162 l0 = __floats2bfloat162_rn(v.x - f0.x, v.y - f0.y);
    __nv_bfloat162 l1 = __floats2bfloat162_rn(v.z - f1.x, v.w - f1.y);
    h.x = *(uint32_t*)&h0; h.y = *(uint32_t*)&h1;
    l.x = *(uint32_t*)&l0; l.y = *(uint32_t*)&l1;
}

// ---------------- merged weight conversion ----------------
struct CvtSeg { const float4* src; uint2* hi; uint2* lo; long n4; };
__global__ void cvtw_all_k(CvtSeg s0, CvtSeg s1, CvtSeg s2, CvtSeg s3) {
    long base = (long)blockIdx.x * blockDim.x + threadIdx.x;
    long stride = (long)gridDim.x * blockDim.x;
    CvtSeg segs[4] = {s0, s1, s2, s3};
#pragma unroll
    for (int si = 0; si < 4; si++) {
        CvtSeg s = segs[si];
        for (long i = base; i < s.n4; i += stride) {
            uint2 h, l;
            cvt_hilo(s.src[i], h, l);
            s.hi[i] = h; s.lo[i] = l;
        }
    }
}

// ---------------- split-K reduction kernels ----------------
__global__ void reduce3_k(const float4* __restrict__ p, float4* __restrict__ o, long n4) {
    long stride = (long)gridDim.x * blockDim.x;
    for (long i = (long)blockIdx.x * blockDim.x + threadIdx.x; i < n4; i += stride) {
        float4 a = p[i], b = p[i + n4], c = p[i + 2 * n4];
        o[i] = make_float4(a.x + b.x + c.x, a.y + b.y + c.y,
                           a.z + b.z + c.z, a.w + b.w + c.w);
    }
}
__global__ void reduce2a_k(const float4* __restrict__ p, float4* __restrict__ X, long n4) {
    long stride = (long)gridDim.x * blockDim.x;
    for (long i = (long)blockIdx.x * blockDim.x + threadIdx.x; i < n4; i += stride) {
        float4 a = p[i], b = p[i + n4], x = X[i];
        X[i] = make_float4(x.x + a.x + b.x, x.y + a.y + b.y,
                           x.z + a.z + b.z, x.w + a.w + b.w);
    }
}

// ============ HMMA GEMM: 128x128 tile, BK=64, 3-stage ============
// MODE 0: split-K partial store: C[z*zC + ...] = A@B(+bias if z==0)
// MODE 2: gather+swiglu->bf16 hi/lo (z=expert)   MODE 3: weighted scatter atomicAdd X (z=expert)
#define BM 128
#define BN 128
#define BK 64
#define A_STRIDE 144
#define B_STRIDE 272
#define OFF_AHI 0
#define OFF_ALO 18432
#define OFF_BHI 36864
#define OFF_BLO 54272
#define STG     71680
#define NSTAGE  3
#define SMEMSZ  (NSTAGE * STG)

template <int MODE>
__global__ __launch_bounds__(256, 1) void gemm_bf(
    const __nv_bfloat16* __restrict__ Ah, const __nv_bfloat16* __restrict__ Al,
    const __nv_bfloat16* __restrict__ Bh, const __nv_bfloat16* __restrict__ Bl,
    const float* __restrict__ bias, float* __restrict__ C,
    __nv_bfloat16* __restrict__ Chi, __nv_bfloat16* __restrict__ Clo,
    int M, int N, int K,
    const int* __restrict__ rowlist, const float* __restrict__ roww,
    const int* __restrict__ cntp, float* __restrict__ X,
    long zA, long zB, long zBias, long zC) {
    extern __shared__ char smem[];
    int tid = threadIdx.x, wid = tid >> 5, lane = tid & 31;

    int ez = blockIdx.z;
    int kbase = 0;
    int NC = K / BK;
    bool dobias = true;
    if (MODE == 0) {
        int nz = gridDim.z, nct = K / BK;
        int per = nct / nz, rem = nct % nz;
        kbase = (per * ez + min(ez, rem)) * BK;
        NC = per + (ez < rem ? 1 : 0);
        C += (size_t)ez * zC;
        dobias = (ez == 0);
    } else if (ez) {
        Ah += (size_t)ez * zA; Al += (size_t)ez * zA;
        Bh += (size_t)ez * zB; Bl += (size_t)ez * zB;
        bias += (size_t)ez * zBias;
        Chi += (size_t)ez * zC; Clo += (size_t)ez * zC;
        rowlist += ez * SEQ; roww += ez * SEQ; cntp += ez;
    }
    int Meff = M;
    if (MODE == 2 || MODE == 3) Meff = *cntp;
    int row0 = blockIdx.x * BM;
    if ((MODE == 2 || MODE == 3) && row0 >= Meff) return;
    int n0 = blockIdx.y * BN;

    int asrc[4];
#pragma unroll
    for (int i = 0; i < 4; i++) {
        int rg = row0 + (tid >> 3) + 32 * i;
        asrc[i] = (rg < Meff) ? ((MODE == 2) ? rowlist[rg] : rg) : -1;
    }
    int ac16 = tid & 7;

    uint32_t sb = smem_u32(smem);
    int wm = wid & 1, wn = wid >> 1;

    float acc[4][4][4];
#pragma unroll
    for (int a = 0; a < 4; a++)
#pragma unroll
        for (int b = 0; b < 4; b++)
#pragma unroll
            for (int c = 0; c < 4; c++) acc[a][b][c] = 0.f;

    auto issue = [&](int c, int s) {
        uint32_t stg = sb + (uint32_t)s * STG;
        int k0 = kbase + c * BK;
#pragma unroll
        for (int i = 0; i < 4; i++) {
            int row = (tid >> 3) + 32 * i;
            bool ok = asrc[i] >= 0;
            size_t go = ok ? ((size_t)asrc[i] * K + k0 + ac16 * 8) : 0;
            uint32_t so = (uint32_t)row * A_STRIDE + (uint32_t)ac16 * 16;
            cpa16(stg + OFF_AHI + so, Ah + go, ok);
            cpa16(stg + OFF_ALO + so, Al + go, ok);
        }
#pragma unroll
        for (int i = 0; i < 4; i++) {
            int idx = tid + 256 * i;
            int k = idx >> 4, c16 = idx & 15;
            int ng = n0 + c16 * 8;
            bool ok = ng < N;
            size_t go = ok ? ((size_t)(k0 + k) * N + ng) : 0;
            uint32_t so = (uint32_t)k * B_STRIDE + (uint32_t)c16 * 16;
            cpa16(stg + OFF_BHI + so, Bh + go, ok);
            cpa16(stg + OFF_BLO + so, Bl + go, ok);
        }
    };

    auto compute = [&](uint32_t stg) {
#pragma unroll
        for (int kk = 0; kk < 4; kk++) {
            uint32_t ah[4][4], al[4][4], bb[2][4];
#pragma unroll
            for (int mi = 0; mi < 4; mi++) {
                uint32_t off = (uint32_t)(wm * 64 + mi * 16 + (lane & 15)) * A_STRIDE
                             + kk * 32 + ((lane >> 4) << 4);
                ldsm4(ah[mi], stg + OFF_AHI + off);
                ldsm4(al[mi], stg + OFF_ALO + off);
            }
#pragma unroll
            for (int bi = 0; bi < 2; bi++) {
                uint32_t off = (uint32_t)(kk * 16 + (lane & 15)) * B_STRIDE
                             + (uint32_t)(wn * 32 + bi * 16 + ((lane >> 4) << 3)) * 2;
                ldsm4t(bb[bi], stg + OFF_BHI + off);
            }
#pragma unroll
            for (int mi = 0; mi < 4; mi++)
#pragma unroll
                for (int bi = 0; bi < 2; bi++) {
                    mma16816(acc[mi][bi * 2],     ah[mi], &bb[bi][0]);
                    mma16816(acc[mi][bi * 2 + 1], ah[mi], &bb[bi][2]);
                    mma16816(acc[mi][bi * 2],     al[mi], &bb[bi][0]);
                    mma16816(acc[mi][bi * 2 + 1], al[mi], &bb[bi][2]);
                }
#pragma unroll
            for (int bi = 0; bi < 2; bi++) {
                uint32_t off = (uint32_t)(kk * 16 + (lane & 15)) * B_STRIDE
                             + (uint32_t)(wn * 32 + bi * 16 + ((lane >> 4) << 3)) * 2;
                ldsm4t(bb[bi], stg + OFF_BLO + off);
            }
#pragma unroll
            for (int mi = 0; mi < 4; mi++)
#pragma unroll
                for (int bi = 0; bi < 2; bi++) {
                    mma16816(acc[mi][bi * 2],     ah[mi], &bb[bi][0]);
                    mma16816(acc[mi][bi * 2 + 1], ah[mi], &bb[bi][2]);
                }
        }
    };

    issue(0, 0); CP_COMMIT();
    if (NC > 1) { issue(1, 1); CP_COMMIT(); }

    for (int c = 0; c < NC; c++) {
        if (c + 1 < NC) CP_WAIT1(); else CP_WAIT0();
        __syncthreads();
        compute(sb + (uint32_t)(c % NSTAGE) * STG);
        if (c + 2 < NC) { issue(c + 2, (c + 2) % NSTAGE); CP_COMMIT(); }
    }

#pragma unroll
    for (int mi = 0; mi < 4; mi++) {
#pragma unroll
        for (int nj = 0; nj < 4; nj++) {
            int rbase = row0 + wm * 64 + mi * 16 + (lane >> 2);
            int c = n0 + wn * 32 + nj * 8 + (lane & 3) * 2;
#pragma unroll
            for (int hf = 0; hf < 2; hf++) {
                int r = rbase + hf * 8;
                if (r >= Meff) continue;
                float v0 = acc[mi][nj][hf * 2], v1 = acc[mi][nj][hf * 2 + 1];
                if (MODE == 0) {
                    if (c < N)     C[(size_t)r * N + c]     = v0 + (dobias ? bias[c] : 0.f);
                    if (c + 1 < N) C[(size_t)r * N + c + 1] = v1 + (dobias ? bias[c + 1] : 0.f);
                } else if (MODE == 2) {
                    if (c < N) {
                        float h0 = v0 + bias[c];
                        float h1 = v1 + bias[c + 1];
                        float glu = fminf(h0, LIMITF);
                        float lin = fminf(fmaxf(h1, -LIMITF), LIMITF);
                        float a = glu * (1.0f / (1.0f + expf(-ALPHAF * glu))) * (lin + 1.0f);
                        __nv_bfloat16 hb = __float2bfloat16(a);
                        size_t o = (size_t)r * INTER + (c >> 1);
                        Chi[o] = hb;
                        Clo[o] = __float2bfloat16(a - __bfloat162float(hb));
                    }
                } else if (MODE == 3) {
                    int tk = rowlist[r];
                    float w = roww[r];
                    if (c < N)     atomicAdd(&X[(size_t)tk * DIMV + c],     w * (v0 + bias[c]));
                    if (c + 1 < N) atomicAdd(&X[(size_t)tk * DIMV + c + 1], w * (v1 + bias[c + 1]));
                }
            }
        }
    }
}

// ---------------- YaRN ----------------
__global__ void yarn_k(float* __restrict__ cosT, float* __restrict__ sinT) {
    int pos = blockIdx.x, d = threadIdx.x;
    double freq = pow(150000.0, (double)d / 32.0);
    double low  = 32.0 * log(4096.0 / (32.0 * 2.0 * M_PI)) / log(150000.0);
    double high = 32.0 * log(4096.0 / (2.0 * M_PI)) / log(150000.0);
    double ramp = ((double)d - low) / (high - low);
    double mm = 1.0 - fmin(fmax(ramp, 0.0), 1.0);
    double inv = (1.0 / (32.0 * freq)) * (1.0 - mm) + (1.0 / freq) * mm;
    double conc = 0.1 * log(32.0) + 1.0;
    double fr = (double)pos * inv;
    cosT[pos * 32 + d] = (float)(cos(fr) * conc);
    sinT[pos * 32 + d] = (float)(sin(fr) * conc);
}

// ---------------- RMSNorm ----------------
__global__ void rmsnorm_k(const float* __restrict__ x, const float* __restrict__ w,
                          float* __restrict__ o32, __nv_bfloat16* __restrict__ oh,
                          __nv_bfloat16* __restrict__ ol) {
    int t = blockIdx.x, tid = threadIdx.x;
    __shared__ float red[256];
    const float* xr = x + (size_t)t * DIMV;
    float s = 0.f;
    for (int i = tid; i < DIMV; i += 256) { float v = xr[i]; s += v * v; }
    red[tid] = s; __syncthreads();
    for (int off = 128; off > 0; off >>= 1) {
        if (tid < off) red[tid] += red[tid + off];
        __syncthreads();
    }
    float inv = 1.0f / sqrtf(red[0] / (float)DIMV + 1e-5f);
    size_t base = (size_t)t * DIMV;
    for (int i = tid; i < DIMV; i += 256) {
        float v = xr[i] * inv * w[i];
        o32[base + i] = v;
        __nv_bfloat16 h = __float2bfloat16(v);
        oh[base + i] = h;
        ol[base + i] = __float2bfloat16(v - __bfloat162float(h));
    }
}

// ---------------- RoPE ----------------
__global__ void rope_k(float* __restrict__ qkv, const float* __restrict__ cosT,
                       const float* __restrict__ sinT) {
    int pos = blockIdx.x;
    for (int idx = threadIdx.x; idx < (NH + NKV) * 32; idx += 256) {
        int hh = idx >> 5, d = idx & 31;
        int col = (hh < NH) ? hh * HD : QD + (hh - NH) * HD;
        float c = cosT[pos * 32 + d], s = sinT[pos * 32 + d];
        float* p = qkv + (size_t)pos * QKVD + col;
        float x1 = p[d], x2 = p[d + 32];
        p[d] = x1 * c - x2 * s;
        p[d + 32] = x2 * c + x1 * s;
    }
}

// ---------------- Attention: MMA, 32 queries x 1 head (R15 best) ----------------
__global__ __launch_bounds__(128) void attn_k(const float* __restrict__ qkv,
                                              const float* __restrict__ sinks,
                                              __nv_bfloat16* __restrict__ outh,
                                              __nv_bfloat16* __restrict__ outl,
                                              int window) {
    __shared__ __align__(16) char q_h[32 * 144];
    __shared__ __align__(16) char q_l[32 * 144];
    __shared__ __align__(16) char kv_h[64 * 144];
    __shared__ __align__(16) char kv_l[64 * 144];
    __shared__ __align__(16) char p_hm[32 * 144];
    __shared__ __align__(16) char p_lm[32 * 144];
    __shared__ float p_s[32][68];
    __shared__ float scale_s[32], m_s[32], l_s[32];

    int qb = blockIdx.x, h = blockIdx.y;
    int q0 = qb * 32, kvh = h >> 3;
    int tid = threadIdx.x, wid = tid >> 5, lane = tid & 31;

    for (int i = tid; i < 32 * 16; i += 128) {
        int row = i >> 4, c = (i & 15) * 4;
        float4 v = *(const float4*)&qkv[(size_t)(q0 + row) * QKVD + h * HD + c];
        uint2 hh, ll; cvt_hilo(v, hh, ll);
        *(uint2*)(q_h + row * 144 + c * 2) = hh;
        *(uint2*)(q_l + row * 144 + c * 2) = ll;
    }
    if (tid < 32) { m_s[tid] = sinks[h]; l_s[tid] = 1.0f; }

    float o_acc[2][2][4];
#pragma unroll
    for (int a = 0; a < 2; a++)
#pragma unroll
        for (int b = 0; b < 2; b++)
#pragma unroll
            for (int c = 0; c < 4; c++) o_acc[a][b][c] = 0.f;

    int jlo = 0;
    if (window > 0) { jlo = q0 - window + 1; if (jlo < 0) jlo = 0; }
    int kcol = QD + kvh * HD, vcol = QD + KDOFF + kvh * HD;
    int srow = tid >> 2, ssub = tid & 3;

    uint32_t qh_b = smem_u32(q_h), ql_b = smem_u32(q_l);
    uint32_t kvh_b = smem_u32(kv_h), kvl_b = smem_u32(kv_l);
    uint32_t ph_b = smem_u32(p_hm), pl_b = smem_u32(p_lm);

    for (int t0 = (jlo >> 6) << 6; t0 <= q0 + 31; t0 += 64) {
        __syncthreads();
        for (int i = tid; i < 64 * 16; i += 128) {
            int row = i >> 4, c = (i & 15) * 4;
            float4 v = *(const float4*)&qkv[(size_t)(t0 + row) * QKVD + kcol + c];
            uint2 hh, ll; cvt_hilo(v, hh, ll);
            *(uint2*)(kv_h + row * 144 + c * 2) = hh;
            *(uint2*)(kv_l + row * 144 + c * 2) = ll;
        }
        __syncthreads();

        float s_acc[2][2][4];
#pragma unroll
        for (int a = 0; a < 2; a++)
#pragma unroll
            for (int b = 0; b < 2; b++)
#pragma unroll
                for (int c = 0; c < 4; c++) s_acc[a][b][c] = 0.f;
#pragma unroll
        for (int kk = 0; kk < 4; kk++) {
            uint32_t qa_h[2][4], qa_l[2][4], kb_h[4], kb_l[4];
#pragma unroll
            for (int mi = 0; mi < 2; mi++) {
                uint32_t off = (uint32_t)(mi * 16 + (lane & 15)) * 144 + kk * 32 + ((lane >> 4) << 4);
                ldsm4(qa_h[mi], qh_b + off);
                ldsm4(qa_l[mi], ql_b + off);
            }
            {
                uint32_t off = (uint32_t)(wid * 16 + (lane & 15)) * 144 + kk * 32 + ((lane >> 4) << 4);
                ldsm4(kb_h, kvh_b + off);
                ldsm4(kb_l, kvl_b + off);
            }
#pragma unroll
            for (int mi = 0; mi < 2; mi++)
#pragma unroll
                for (int nj = 0; nj < 2; nj++) {
                    uint32_t bh2[2] = {kb_h[nj], kb_h[nj + 2]};
                    uint32_t bl2[2] = {kb_l[nj], kb_l[nj + 2]};
                    mma16816(s_acc[mi][nj], qa_h[mi], bh2);
                    mma16816(s_acc[mi][nj], qa_l[mi], bh2);
                    mma16816(s_acc[mi][nj], qa_h[mi], bl2);
                }
        }
#pragma unroll
        for (int mi = 0; mi < 2; mi++)
#pragma unroll
            for (int nj = 0; nj < 2; nj++)
#pragma unroll
                for (int hf = 0; hf < 2; hf++) {
                    int r = mi * 16 + (lane >> 2) + hf * 8;
                    int cc = wid * 16 + nj * 8 + (lane & 3) * 2;
                    int ii = q0 + r;
#pragma unroll
                    for (int e = 0; e < 2; e++) {
                        int jj = t0 + cc + e;
                        bool ok = (jj <= ii) && (window == 0 || (ii - jj) < window);
                        p_s[r][cc + e] = ok ? s_acc[mi][nj][hf * 2 + e] * SM_SCALE : -1e30f;
                    }
                }
        __syncthreads();

        {
            float mloc = -1e30f;
#pragma unroll
            for (int j = 0; j < 16; j++) mloc = fmaxf(mloc, p_s[srow][ssub * 16 + j]);
            mloc = fmaxf(mloc, __shfl_xor_sync(0xffffffffu, mloc, 1));
            mloc = fmaxf(mloc, __shfl_xor_sync(0xffffffffu, mloc, 2));
            float mold = m_s[srow];
            float mn = fmaxf(mold, mloc);
            float sum = 0.f;
#pragma unroll
            for (int j = 0; j < 16; j++) {
                float e = __expf(p_s[srow][ssub * 16 + j] - mn);
                p_s[srow][ssub * 16 + j] = e;
                sum += e;
            }
            sum += __shfl_xor_sync(0xffffffffu, sum, 1);
            sum += __shfl_xor_sync(0xffffffffu, sum, 2);
            if (ssub == 0) {
                float rs = __expf(mold - mn);
                l_s[srow] = l_s[srow] * rs + sum;
                m_s[srow] = mn;
                scale_s[srow] = rs;
            }
        }
        __syncthreads();

#pragma unroll
        for (int mi = 0; mi < 2; mi++)
#pragma unroll
            for (int hf = 0; hf < 2; hf++) {
                int r = mi * 16 + (lane >> 2) + hf * 8;
                float s = scale_s[r];
#pragma unroll
                for (int nj = 0; nj < 2; nj++) {
                    o_acc[mi][nj][hf * 2]     *= s;
                    o_acc[mi][nj][hf * 2 + 1] *= s;
                }
            }
#pragma unroll
        for (int j = 0; j < 16; j += 2) {
            int c = ssub * 16 + j;
            float v0 = p_s[srow][c], v1 = p_s[srow][c + 1];
            __nv_bfloat162 hh = __floats2bfloat162_rn(v0, v1);
            float2 f = __bfloat1622float2(hh);
            __nv_bfloat162 ll = __floats2bfloat162_rn(v0 - f.x, v1 - f.y);
            *(uint32_t*)(p_hm + srow * 144 + c * 2) = *(uint32_t*)&hh;
            *(uint32_t*)(p_lm + srow * 144 + c * 2) = *(uint32_t*)&ll;
        }
        for (int i = tid; i < 64 * 16; i += 128) {
            int row = i >> 4, c = (i & 15) * 4;
            float4 v = *(const float4*)&qkv[(size_t)(t0 + row) * QKVD + vcol + c];
            uint2 hh, ll; cvt_hilo(v, hh, ll);
            *(uint2*)(kv_h + row * 144 + c * 2) = hh;
            *(uint2*)(kv_l + row * 144 + c * 2) = ll;
        }
        __syncthreads();

#pragma unroll
        for (int kk = 0; kk < 4; kk++) {
            uint32_t pa_h[2][4], pa_l[2][4], vb_h[4], vb_l[4];
#pragma unroll
            for (int mi = 0; mi < 2; mi++) {
                uint32_t off = (uint32_t)(mi * 16 + (lane & 15)) * 144 + kk * 32 + ((lane >> 4) << 4);
                ldsm4(pa_h[mi], ph_b + off);
                ldsm4(pa_l[mi], pl_b + off);
            }
            {
                uint32_t off = (uint32_t)(kk * 16 + (lane & 15)) * 144
                             + (uint32_t)(wid * 16 + ((lane >> 4) << 3)) * 2;
                ldsm4t(vb_h, kvh_b + off);
                ldsm4t(vb_l, kvl_b + off);
            }
#pragma unroll
            for (int mi = 0; mi < 2; mi++)
#pragma unroll
                for (int nj = 0; nj < 2; nj++) {
                    mma16816(o_acc[mi][nj], pa_h[mi], &vb_h[nj * 2]);
                    mma16816(o_acc[mi][nj], pa_l[mi], &vb_h[nj * 2]);
                    mma16816(o_acc[mi][nj], pa_h[mi], &vb_l[nj * 2]);
                }
        }
    }
    __syncthreads();
    if (tid < 32) scale_s[tid] = 1.0f / l_s[tid];
    __syncthreads();
#pragma unroll
    for (int mi = 0; mi < 2; mi++)
#pragma unroll
        for (int nj = 0; nj < 2; nj++)
#pragma unroll
            for (int hf = 0; hf < 2; hf++) {
                int r = mi * 16 + (lane >> 2) + hf * 8;
                float li = scale_s[r];
                int cc = wid * 16 + nj * 8 + (lane & 3) * 2;
#pragma unroll
                for (int e = 0; e < 2; e++) {
                    float v = o_acc[mi][nj][hf * 2 + e] * li;
                    size_t o = (size_t)(q0 + r) * QD + h * HD + cc + e;
                    __nv_bfloat16 hb = __float2bfloat16(v);
                    outh[o] = hb;
                    outl[o] = __float2bfloat16(v - __bfloat162float(hb));
                }
            }
}

// ---------------- gate + routing ----------------
__global__ void gate_k(const float* __restrict__ t, const float* __restrict__ gw,
                       const float* __restrict__ gb, int* __restrict__ sel,
                       float* __restrict__ selw) {
    int tk = blockIdx.x, tid = threadIdx.x;
    __shared__ float red[4][128];
    float p[4] = {0.f, 0.f, 0.f, 0.f};
    const float* tr = t + (size_t)tk * DIMV;
    for (int k = tid; k < DIMV; k += 128) {
        float v = tr[k];
#pragma unroll
        for (int e = 0; e < 4; e++) p[e] += v * gw[k * 4 + e];
    }
#pragma unroll
    for (int e = 0; e < 4; e++) red[e][tid] = p[e];
    __syncthreads();
    for (int off = 64; off > 0; off >>= 1) {
        if (tid < off)
#pragma unroll
            for (int e = 0; e < 4; e++) red[e][tid] += red[e][tid + off];
        __syncthreads();
    }
    if (tid == 0) {
        float v[4];
#pragma unroll
        for (int e = 0; e < 4; e++) v[e] = red[e][0] + gb[e];
        int i0 = 0;
        for (int e = 1; e < 4; e++) if (v[e] > v[i0]) i0 = e;
        int i1 = (i0 == 0) ? 1 : 0;
        for (int e = 0; e < 4; e++) if (e != i0 && v[e] > v[i1]) i1 = e;
        float ex = expf(v[i1] - v[i0]);
        float den = 1.0f + ex;
        sel[tk * 2] = i0; sel[tk * 2 + 1] = i1;
        selw[tk * 2] = 1.0f / den; selw[tk * 2 + 1] = ex / den;
    }
}

__global__ void build_lists_k(const int* __restrict__ sel, const float* __restrict__ selw,
                              int* __restrict__ list, float* __restrict__ wgt,
                              int* __restrict__ cnt) {
    int w = threadIdx.x >> 5, lane = threadIdx.x & 31;
    if (w >= NEXP) return;
    int e = w, c = 0;
    for (int base = 0; base < SEQ; base += 32) {
        int tk = base + lane;
        int s0 = sel[tk * 2], s1 = sel[tk * 2 + 1];
        bool f = (s0 == e) || (s1 == e);
        float wv = (s0 == e) ? selw[tk * 2] : selw[tk * 2 + 1];
        unsigned msk = __ballot_sync(0xffffffffu, f);
        if (f) {
            int pos = c + __popc(msk & ((1u << lane) - 1u));
            list[e * SEQ + pos] = tk;
            wgt[e * SEQ + pos]  = wv;
        }
        c += __popc(msk);
    }
    if (lane == 0) cnt[e] = c;
}

// ---------------- host ----------------
extern "C" void kernel_launch(void* const* d_in, const int* in_sizes, int n_in,
                              void* d_out, int out_size) {
    const float* x_in  = (const float*)d_in[0];
    const float* rms1w = (const float*)d_in[1];
    const float* qkvw  = (const float*)d_in[2];
    const float* qkvb  = (const float*)d_in[3];
    const float* outw  = (const float*)d_in[4];
    const float* outb  = (const float*)d_in[5];
    const float* sinks = (const float*)d_in[6];
    const float* rms2w = (const float*)d_in[7];
    const float* gatew = (const float*)d_in[8];
    const float* gateb = (const float*)d_in[9];
    const float* w1    = (const float*)d_in[10];
    const float* b1    = (const float*)d_in[11];
    const float* w2    = (const float*)d_in[12];
    const float* b2    = (const float*)d_in[13];

    float *t32, *qkv, *qkvp, *outp, *cosT, *sinT, *selw, *wgt;
    __nv_bfloat16 *th, *tl, *ah, *al, *acth, *actl;
    __nv_bfloat16 *qwh, *qwl, *owh, *owl, *w1h, *w1l, *w2h, *w2l;
    int *sel, *list, *cnt;
    cudaGetSymbolAddress((void**)&t32, g_t32);
    cudaGetSymbolAddress((void**)&th, g_th);
    cudaGetSymbolAddress((void**)&tl, g_tl);
    cudaGetSymbolAddress((void**)&qkv, g_qkv);
    cudaGetSymbolAddress((void**)&qkvp, g_qkvp);
    cudaGetSymbolAddress((void**)&outp, g_outp);
    cudaGetSymbolAddress((void**)&ah, g_ah);
    cudaGetSymbolAddress((void**)&al, g_al);
    cudaGetSymbolAddress((void**)&acth, g_acth);
    cudaGetSymbolAddress((void**)&actl, g_actl);
    cudaGetSymbolAddress((void**)&cosT, g_cos);
    cudaGetSymbolAddress((void**)&sinT, g_sin);
    cudaGetSymbolAddress((void**)&sel, g_sel);
    cudaGetSymbolAddress((void**)&selw, g_selw);
    cudaGetSymbolAddress((void**)&list, g_list);
    cudaGetSymbolAddress((void**)&wgt, g_wgt);
    cudaGetSymbolAddress((void**)&cnt, g_cnt);
    cudaGetSymbolAddress((void**)&qwh, g_qkvw_h);
    cudaGetSymbolAddress((void**)&qwl, g_qkvw_l);
    cudaGetSymbolAddress((void**)&owh, g_outw_h);
    cudaGetSymbolAddress((void**)&owl, g_outw_l);
    cudaGetSymbolAddress((void**)&w1h, g_w1_h);
    cudaGetSymbolAddress((void**)&w1l, g_w1_l);
    cudaGetSymbolAddress((void**)&w2h, g_w2_h);
    cudaGetSymbolAddress((void**)&w2l, g_w2_l);

    cudaFuncSetAttribute(gemm_bf<0>, cudaFuncAttributeMaxDynamicSharedMemorySize, SMEMSZ);
    cudaFuncSetAttribute(gemm_bf<2>, cudaFuncAttributeMaxDynamicSharedMemorySize, SMEMSZ);
    cudaFuncSetAttribute(gemm_bf<3>, cudaFuncAttributeMaxDynamicSharedMemorySize, SMEMSZ);

    float* X = (float*)d_out;
    cudaMemcpyAsync(X, x_in, sizeof(float) * SEQ * DIMV, cudaMemcpyDeviceToDevice);
    yarn_k<<<SEQ, 32>>>(cosT, sinT);

    CvtSeg s0 = {(const float4*)qkvw, (uint2*)qwh, (uint2*)qwl, NQKVW / 4};
    CvtSeg s1 = {(const float4*)outw, (uint2*)owh, (uint2*)owl, NOUTW / 4};
    CvtSeg s2 = {(const float4*)w1,   (uint2*)w1h, (uint2*)w1l, NW1 / 4};
    CvtSeg s3 = {(const float4*)w2,   (uint2*)w2h, (uint2*)w2l, NW2 / 4};
    cvtw_all_k<<<4736, 256>>>(s0, s1, s2, s3);

    for (int layer = 0; layer < 2; layer++) {
        rmsnorm_k<<<SEQ, 256>>>(X, rms1w + (size_t)layer * DIMV, t32, th, tl);
        // qkv: split-K=3 into partials, then reduce
        gemm_bf<0><<<dim3(SEQ / 128, QKVD / 128, 3), 256, SMEMSZ>>>(
            th, tl, qwh + (size_t)layer * DIMV * QKVD, qwl + (size_t)layer * DIMV * QKVD,
            qkvb + (size_t)layer * QKVD, qkvp, nullptr, nullptr,
            SEQ, QKVD, DIMV, nullptr, nullptr, nullptr, nullptr,
            0, 0, 0, (long)SEQ * QKVD);
        reduce3_k<<<1184, 256>>>((const float4*)qkvp, (float4*)qkv, (long)SEQ * QKVD / 4);
        rope_k<<<SEQ, 256>>>(qkv, cosT, sinT);
        attn_k<<<dim3(SEQ / 32, NH), 128>>>(qkv, sinks + (size_t)layer * NH, ah, al,
                                            (layer % 2 == 0) ? 128 : 0);
        // out-proj: split-K=2 into partials, then reduce-add into X
        gemm_bf<0><<<dim3(SEQ / 128, (DIMV + 127) / 128, 2), 256, SMEMSZ>>>(
            ah, al, owh + (size_t)layer * QD * DIMV, owl + (size_t)layer * QD * DIMV,
            outb + (size_t)layer * DIMV, outp, nullptr, nullptr,
            SEQ, DIMV, QD, nullptr, nullptr, nullptr, nullptr,
            0, 0, 0, (long)SEQ * DIMV);
        reduce2a_k<<<1184, 256>>>((const float4*)outp, (float4*)X, (long)SEQ * DIMV / 4);

        rmsnorm_k<<<SEQ, 256>>>(X, rms2w + (size_t)layer * DIMV, t32, th, tl);
        gate_k<<<SEQ, 128>>>(t32, gatew + (size_t)layer * DIMV * NEXP,
                             gateb + (size_t)layer * NEXP, sel, selw);
        build_lists_k<<<1, 128>>>(sel, selw, list, wgt, cnt);

        gemm_bf<2><<<dim3(SEQ / 128, (2 * INTER) / 128, NEXP), 256, SMEMSZ>>>(
            th, tl,
            w1h + (size_t)layer * NEXP * DIMV * 2 * INTER,
            w1l + (size_t)layer * NEXP * DIMV * 2 * INTER,
            b1 + (size_t)layer * NEXP * 2 * INTER,
            nullptr, acth, actl,
            0, 2 * INTER, DIMV, list, wgt, cnt, nullptr,
            0, (long)DIMV * 2 * INTER, 2 * INTER, (long)SEQ * INTER);

        gemm_bf<3><<<dim3(SEQ / 128, (DIMV + 127) / 128, NEXP), 256, SMEMSZ>>>(
            acth, actl,
            w2h + (size_t)layer * NEXP * INTER * DIMV,
            w2l + (size_t)layer * NEXP * INTER * DIMV,
            b2 + (size_t)layer * NEXP * DIMV, nullptr, nullptr, nullptr,
            0, DIMV, INTER, list, wgt, cnt, X,
            (long)SEQ * INTER, (long)INTER * DIMV, DIMV, 0);
    }
    (void)in_sizes; (void)n_in; (void)out_size;
}